// round 1
// baseline (speedup 1.0000x reference)
#include <cuda_runtime.h>
#include <cuda_bf16.h>

#define N_POINTS 64
#define N_ANGS   2016   // 64*63/2
#define NCOLS_BLK 256

// R stored k-major: g_R[k*64 + i] = mus[i] * R[i][k]
__device__ float g_R[N_POINTS * N_POINTS];

// ---------------------------------------------------------------------------
// Kernel 1: build the composite rotation matrix R (one block, 64 threads).
// Thread j computes column j of R = (G_2016 ... G_1) e_j, fully in registers.
// The (it, ib) pair sequence is compile-time constant -> full unroll keeps
// r[64] statically indexed (no local-memory spills, no dynamic indexing).
// ---------------------------------------------------------------------------
__global__ void build_R_kernel(const float* __restrict__ angles,
                               const float* __restrict__ mus) {
    __shared__ float2 cs[N_ANGS];
    const int tid = threadIdx.x;  // 0..63, = column index k of R

    // Precompute cos/sin for all 2016 angles cooperatively.
    for (int a = tid; a < N_ANGS; a += N_POINTS) {
        float ang = angles[a];
        cs[a] = make_float2(cosf(ang), sinf(ang));
    }
    __syncthreads();

    float r[N_POINTS];
#pragma unroll
    for (int i = 0; i < N_POINTS; ++i) r[i] = (i == tid) ? 1.0f : 0.0f;

    int idx = 0;
#pragma unroll
    for (int it = 0; it < N_POINTS - 1; ++it) {
#pragma unroll
        for (int ib = it + 1; ib < N_POINTS; ++ib) {
            float2 a = cs[idx];
            ++idx;
            float vt = r[it];
            float vb = r[ib];
            // vt' = c*vt - s*vb ; vb' = s*vt + c*vb
            r[it] = fmaf(a.x, vt, -a.y * vb);
            r[ib] = fmaf(a.y, vt,  a.x * vb);
        }
    }

    // Fold the row scaling by mus into R, store k-major.
#pragma unroll
    for (int i = 0; i < N_POINTS; ++i) {
        g_R[tid * N_POINTS + i] = r[i] * mus[i];
    }
}

// ---------------------------------------------------------------------------
// Kernel 2: out[64, N] = R @ X.  One thread per column; acc[64] in registers,
// R broadcast from shared memory via LDS.128. K unrolled x4 for load MLP.
// ---------------------------------------------------------------------------
__global__ __launch_bounds__(NCOLS_BLK)
void apply_R_kernel(const float* __restrict__ X,
                    float* __restrict__ out,
                    int N) {
    __shared__ float Rs[N_POINTS * N_POINTS];
    for (int t = threadIdx.x; t < N_POINTS * N_POINTS; t += blockDim.x) {
        Rs[t] = g_R[t];
    }
    __syncthreads();

    const int col = blockIdx.x * NCOLS_BLK + threadIdx.x;
    if (col >= N) return;

    float acc[N_POINTS];
#pragma unroll
    for (int i = 0; i < N_POINTS; ++i) acc[i] = 0.0f;

    const float* xp = X + col;
    const float4* R4 = reinterpret_cast<const float4*>(Rs);

    for (int k0 = 0; k0 < N_POINTS; k0 += 4) {
        // 4 outstanding global loads per iteration (MLP=4).
        float x0 = xp[(k0 + 0) * N];
        float x1 = xp[(k0 + 1) * N];
        float x2 = xp[(k0 + 2) * N];
        float x3 = xp[(k0 + 3) * N];

#pragma unroll
        for (int i4 = 0; i4 < N_POINTS / 4; ++i4) {
            float4 r0 = R4[(k0 + 0) * 16 + i4];
            acc[4 * i4 + 0] = fmaf(r0.x, x0, acc[4 * i4 + 0]);
            acc[4 * i4 + 1] = fmaf(r0.y, x0, acc[4 * i4 + 1]);
            acc[4 * i4 + 2] = fmaf(r0.z, x0, acc[4 * i4 + 2]);
            acc[4 * i4 + 3] = fmaf(r0.w, x0, acc[4 * i4 + 3]);
        }
#pragma unroll
        for (int i4 = 0; i4 < N_POINTS / 4; ++i4) {
            float4 r1 = R4[(k0 + 1) * 16 + i4];
            acc[4 * i4 + 0] = fmaf(r1.x, x1, acc[4 * i4 + 0]);
            acc[4 * i4 + 1] = fmaf(r1.y, x1, acc[4 * i4 + 1]);
            acc[4 * i4 + 2] = fmaf(r1.z, x1, acc[4 * i4 + 2]);
            acc[4 * i4 + 3] = fmaf(r1.w, x1, acc[4 * i4 + 3]);
        }
#pragma unroll
        for (int i4 = 0; i4 < N_POINTS / 4; ++i4) {
            float4 r2 = R4[(k0 + 2) * 16 + i4];
            acc[4 * i4 + 0] = fmaf(r2.x, x2, acc[4 * i4 + 0]);
            acc[4 * i4 + 1] = fmaf(r2.y, x2, acc[4 * i4 + 1]);
            acc[4 * i4 + 2] = fmaf(r2.z, x2, acc[4 * i4 + 2]);
            acc[4 * i4 + 3] = fmaf(r2.w, x2, acc[4 * i4 + 3]);
        }
#pragma unroll
        for (int i4 = 0; i4 < N_POINTS / 4; ++i4) {
            float4 r3 = R4[(k0 + 3) * 16 + i4];
            acc[4 * i4 + 0] = fmaf(r3.x, x3, acc[4 * i4 + 0]);
            acc[4 * i4 + 1] = fmaf(r3.y, x3, acc[4 * i4 + 1]);
            acc[4 * i4 + 2] = fmaf(r3.z, x3, acc[4 * i4 + 2]);
            acc[4 * i4 + 3] = fmaf(r3.w, x3, acc[4 * i4 + 3]);
        }
    }

#pragma unroll
    for (int i = 0; i < N_POINTS; ++i) {
        out[i * N + col] = acc[i];
    }
}

// ---------------------------------------------------------------------------
// Launch: inputs in metadata order: X [64*500000] f32, angles [2016] f32,
// mus [64] f32. Output: [64*500000] f32.
// ---------------------------------------------------------------------------
extern "C" void kernel_launch(void* const* d_in, const int* in_sizes, int n_in,
                              void* d_out, int out_size) {
    const float* X      = (const float*)d_in[0];
    const float* angles = (const float*)d_in[1];
    const float* mus    = (const float*)d_in[2];
    float* out = (float*)d_out;

    const int N = in_sizes[0] / N_POINTS;  // 500000

    build_R_kernel<<<1, N_POINTS>>>(angles, mus);

    int grid = (N + NCOLS_BLK - 1) / NCOLS_BLK;
    apply_R_kernel<<<grid, NCOLS_BLK>>>(X, out, N);
}

// round 3
// speedup vs baseline: 1.4104x; 1.4104x over previous
#include <cuda_runtime.h>
#include <cuda_bf16.h>

#define NP   64
#define NANG 2016      // 64*63/2
#define TPB  256

// R stored k-major, row-scaled: g_R[k*64 + i] = mus[i] * R[i][k]
__device__ float g_R[NP * NP];

// ---------------------------------------------------------------------------
// f32x2 packed helpers (sm_103a): FFMA2 only reachable via PTX fma.rn.f32x2
// ---------------------------------------------------------------------------
__device__ __forceinline__ unsigned long long ffma2(unsigned long long a,
                                                    unsigned long long b,
                                                    unsigned long long c) {
    unsigned long long d;
    asm("fma.rn.f32x2 %0, %1, %2, %3;" : "=l"(d) : "l"(a), "l"(b), "l"(c));
    return d;
}
__device__ __forceinline__ unsigned long long splat2(float x) {
    unsigned long long d;
    asm("mov.b64 %0, {%1, %1};" : "=l"(d) : "f"(x));
    return d;
}
__device__ __forceinline__ float2 unpack2(unsigned long long v) {
    float2 r;
    asm("mov.b64 {%0, %1}, %2;" : "=f"(r.x), "=f"(r.y) : "l"(v));
    return r;
}

// ---------------------------------------------------------------------------
// Kernel 1: build composite rotation matrix R (1 block, 64 threads).
// Thread j holds column j of R in registers; pair sequence is compile-time
// constant -> fully unrolled, statically indexed (no local-mem spills).
// ---------------------------------------------------------------------------
__global__ void build_R_kernel(const float* __restrict__ angles,
                               const float* __restrict__ mus) {
    __shared__ float2 cs[NANG];
    const int tid = threadIdx.x;  // 0..63 = column index of R

    for (int a = tid; a < NANG; a += NP) {
        float s, c;
        sincosf(angles[a], &s, &c);
        cs[a] = make_float2(c, s);
    }
    __syncthreads();

    float r[NP];
#pragma unroll
    for (int i = 0; i < NP; ++i) r[i] = (i == tid) ? 1.0f : 0.0f;

    int idx = 0;
#pragma unroll
    for (int it = 0; it < NP - 1; ++it) {
#pragma unroll
        for (int ib = it + 1; ib < NP; ++ib) {
            float2 a = cs[idx];
            ++idx;
            float vt = r[it];
            float vb = r[ib];
            r[it] = fmaf(a.x, vt, -a.y * vb);
            r[ib] = fmaf(a.y, vt,  a.x * vb);
        }
    }

#pragma unroll
    for (int i = 0; i < NP; ++i) g_R[tid * NP + i] = r[i] * mus[i];
}

// ---------------------------------------------------------------------------
// Kernel 2: out[64, N] = R @ X via f32x2 packed FMA.
// Tile: 256 threads = 4 row-groups x 64 col-slots; thread computes 16 rows x
// 4 cols. Rows packed pairwise into f32x2 lanes; R row-pairs come straight
// from shared as ulonglong2 (LDS.128, warp-broadcast, zero packing movs).
// X columns via LDG.128, splat per column per k.
// ---------------------------------------------------------------------------
__global__ __launch_bounds__(TPB, 2)
void apply_R_kernel(const float* __restrict__ X,
                    float* __restrict__ out,
                    int N) {
    __shared__ __align__(16) float Rs[NP * NP];
    for (int t = threadIdx.x; t < NP * NP; t += TPB) Rs[t] = g_R[t];
    __syncthreads();

    const int rg  = threadIdx.x >> 6;          // row group 0..3 (rows rg*16..rg*16+15)
    const int cl  = threadIdx.x & 63;          // column slot
    const int col = blockIdx.x * TPB + cl * 4; // 256 columns per block
    if (col >= N) return;                      // N % 4 == 0 -> whole-float4 guard

    // acc[p][j]: f32x2 over rows (rg*16+2p, rg*16+2p+1), column col+j
    unsigned long long acc[8][4];
#pragma unroll
    for (int p = 0; p < 8; ++p)
#pragma unroll
        for (int j = 0; j < 4; ++j) acc[p][j] = 0ull;

    const ulonglong2* Rs2 = reinterpret_cast<const ulonglong2*>(Rs);
    const int rbase = rg * 4;                  // ull2 offset inside one k-row (16 ull2/k)
    const float* xp = X + col;

#define DO_K(kk, xv)                                                             \
    {                                                                            \
        unsigned long long xs0 = splat2((xv).x);                                 \
        unsigned long long xs1 = splat2((xv).y);                                 \
        unsigned long long xs2 = splat2((xv).z);                                 \
        unsigned long long xs3 = splat2((xv).w);                                 \
        ulonglong2 q0 = Rs2[(kk) * 16 + rbase + 0];                              \
        ulonglong2 q1 = Rs2[(kk) * 16 + rbase + 1];                              \
        ulonglong2 q2 = Rs2[(kk) * 16 + rbase + 2];                              \
        ulonglong2 q3 = Rs2[(kk) * 16 + rbase + 3];                              \
        acc[0][0] = ffma2(q0.x, xs0, acc[0][0]);                                 \
        acc[0][1] = ffma2(q0.x, xs1, acc[0][1]);                                 \
        acc[0][2] = ffma2(q0.x, xs2, acc[0][2]);                                 \
        acc[0][3] = ffma2(q0.x, xs3, acc[0][3]);                                 \
        acc[1][0] = ffma2(q0.y, xs0, acc[1][0]);                                 \
        acc[1][1] = ffma2(q0.y, xs1, acc[1][1]);                                 \
        acc[1][2] = ffma2(q0.y, xs2, acc[1][2]);                                 \
        acc[1][3] = ffma2(q0.y, xs3, acc[1][3]);                                 \
        acc[2][0] = ffma2(q1.x, xs0, acc[2][0]);                                 \
        acc[2][1] = ffma2(q1.x, xs1, acc[2][1]);                                 \
        acc[2][2] = ffma2(q1.x, xs2, acc[2][2]);                                 \
        acc[2][3] = ffma2(q1.x, xs3, acc[2][3]);                                 \
        acc[3][0] = ffma2(q1.y, xs0, acc[3][0]);                                 \
        acc[3][1] = ffma2(q1.y, xs1, acc[3][1]);                                 \
        acc[3][2] = ffma2(q1.y, xs2, acc[3][2]);                                 \
        acc[3][3] = ffma2(q1.y, xs3, acc[3][3]);                                 \
        acc[4][0] = ffma2(q2.x, xs0, acc[4][0]);                                 \
        acc[4][1] = ffma2(q2.x, xs1, acc[4][1]);                                 \
        acc[4][2] = ffma2(q2.x, xs2, acc[4][2]);                                 \
        acc[4][3] = ffma2(q2.x, xs3, acc[4][3]);                                 \
        acc[5][0] = ffma2(q2.y, xs0, acc[5][0]);                                 \
        acc[5][1] = ffma2(q2.y, xs1, acc[5][1]);                                 \
        acc[5][2] = ffma2(q2.y, xs2, acc[5][2]);                                 \
        acc[5][3] = ffma2(q2.y, xs3, acc[5][3]);                                 \
        acc[6][0] = ffma2(q3.x, xs0, acc[6][0]);                                 \
        acc[6][1] = ffma2(q3.x, xs1, acc[6][1]);                                 \
        acc[6][2] = ffma2(q3.x, xs2, acc[6][2]);                                 \
        acc[6][3] = ffma2(q3.x, xs3, acc[6][3]);                                 \
        acc[7][0] = ffma2(q3.y, xs0, acc[7][0]);                                 \
        acc[7][1] = ffma2(q3.y, xs1, acc[7][1]);                                 \
        acc[7][2] = ffma2(q3.y, xs2, acc[7][2]);                                 \
        acc[7][3] = ffma2(q3.y, xs3, acc[7][3]);                                 \
    }

#pragma unroll 1
    for (int kb = 0; kb < NP; kb += 4) {
        // 4 outstanding LDG.128 per iteration (MLP=4)
        float4 xa = *reinterpret_cast<const float4*>(xp + (size_t)(kb + 0) * N);
        float4 xb = *reinterpret_cast<const float4*>(xp + (size_t)(kb + 1) * N);
        float4 xc = *reinterpret_cast<const float4*>(xp + (size_t)(kb + 2) * N);
        float4 xd = *reinterpret_cast<const float4*>(xp + (size_t)(kb + 3) * N);
        DO_K(kb + 0, xa);
        DO_K(kb + 1, xb);
        DO_K(kb + 2, xc);
        DO_K(kb + 3, xd);
    }
#undef DO_K

    // Write out: unpack row pairs, store float4 per row (coalesced).
    const int row0 = rg * 16;
#pragma unroll
    for (int p = 0; p < 8; ++p) {
        float2 u0 = unpack2(acc[p][0]);
        float2 u1 = unpack2(acc[p][1]);
        float2 u2 = unpack2(acc[p][2]);
        float2 u3 = unpack2(acc[p][3]);
        float4 lo = make_float4(u0.x, u1.x, u2.x, u3.x);
        float4 hi = make_float4(u0.y, u1.y, u2.y, u3.y);
        *reinterpret_cast<float4*>(out + (size_t)(row0 + 2 * p + 0) * N + col) = lo;
        *reinterpret_cast<float4*>(out + (size_t)(row0 + 2 * p + 1) * N + col) = hi;
    }
}

// ---------------------------------------------------------------------------
// Inputs (metadata order): X [64*500000] f32, angles [2016] f32, mus [64] f32.
// Output: [64*500000] f32.
// ---------------------------------------------------------------------------
extern "C" void kernel_launch(void* const* d_in, const int* in_sizes, int n_in,
                              void* d_out, int out_size) {
    const float* X      = (const float*)d_in[0];
    const float* angles = (const float*)d_in[1];
    const float* mus    = (const float*)d_in[2];
    float* out = (float*)d_out;

    const int N = in_sizes[0] / NP;  // 500000

    build_R_kernel<<<1, NP>>>(angles, mus);

    int grid = (N + TPB - 1) / TPB;  // 256 columns per block
    apply_R_kernel<<<grid, TPB>>>(X, out, N);
}